// round 16
// baseline (speedup 1.0000x reference)
#include <cuda_runtime.h>
#include <cuda_pipeline_primitives.h>

// SSIM loss, fused single pass + fused finalize. B=64, H=W=384, WIN=7.
//
// R15 (= R14 retry; infra failure): warp-autonomous pipelines. Each warp owns
// a 64-output-col slice (+7 halo) with a private 8-slot smem row ring staged
// by its own cp.async commit groups. Per row: wait_prior(6) -> syncwarp ->
// compute -> stage r+7. NO __syncthreads in the main loop: warps drift freely
// so memory stalls are mutually covered. Ring / emit / divide-pairing math
// identical to R13. NBANDS=9.

#define BATCH    64
#define HH       384
#define WW       384
#define WIN      7
#define OH       378
#define OW       378
#define NBANDS   9
#define OROWS    42                     // output rows per band
#define INROWS   48                     // input rows per band
#define NTHREADS 192
#define NWARPS   6
#define WCOLS    64                     // output cols per warp
#define TCOLS    72                     // tile cols per warp (64 + 7 halo + pad)
#define DEPTH    8                      // row slots per warp (power of 2)
#define NCTAS    (NBANDS * BATCH)       // 576

__device__ float g_part[NCTAS];
__device__ unsigned int g_count;        // zero-init; last block resets to 0

__global__ __launch_bounds__(NTHREADS, 3) void ssim_main_kernel(
    const float* __restrict__ X, const float* __restrict__ Y,
    const float* __restrict__ data_range, float* __restrict__ out)
{
    __shared__ float tile[NWARPS][DEPTH][2][TCOLS];   // per-warp private ring
    __shared__ float warpsum[NWARPS];
    __shared__ double dsum[NWARPS];
    __shared__ int is_last;

    const int t = threadIdx.x;
    const int w = t >> 5;
    const int l = t & 31;
    const int band = blockIdx.x;
    const int b    = blockIdx.y;
    const int row0 = band * OROWS;
    const int cbase = w * WCOLS;        // first global col of this warp's slice
    const int cl = 2 * l;               // local col within tile

    const float L     = data_range[b];
    const float C1s   = (0.49f * L) * (0.49f * L);   // C1 * 49^2
    const float C2s   = (1.47f * L) * (1.47f * L);   // C2 * 49^2
    const float covn  = 49.0f / 48.0f;
    const float covn2 = 2.0f * covn;

    const float* __restrict__ Xb = X + (size_t)b * HH * WW;
    const float* __restrict__ Yb = Y + (size_t)b * HH * WW;

    // zero entire tile once (covers cols >= 384 for last warp + halo pad)
    for (int e = t; e < NWARPS * DEPTH * 2 * TCOLS; e += NTHREADS)
        ((float*)tile)[e] = 0.f;
    __syncthreads();

    // rings: 4 stats x 2 cols x 7 (static idx via unroll)
    float rx0[WIN], rx1[WIN], ry0[WIN], ry1[WIN];
    float rp0[WIN], rp1[WIN], rq0[WIN], rq1[WIN];   // p = xx+yy, q = xy
#pragma unroll
    for (int i = 0; i < WIN; i++) {
        rx0[i]=0.f; rx1[i]=0.f; ry0[i]=0.f; ry1[i]=0.f;
        rp0[i]=0.f; rp1[i]=0.f; rq0[i]=0.f; rq1[i]=0.f;
    }
    float Wx0=0.f, Wx1=0.f, Wy0=0.f, Wy1=0.f;
    float Wp0=0.f, Wp1=0.f, Wq0=0.f, Wq1=0.f;
    float acc = 0.f;
    float pn = 0.f, pd = 1.f;
    bool  have = false;

    // stage one row (r) of this warp's slice; ALWAYS commits (group accounting)
    const bool loader = (l < 18) && (cbase + 4 * l < WW);   // 18 float4 chunks
    auto stage = [&](int r) {
        if (r < INROWS && loader) {
            const size_t off = (size_t)(row0 + r) * WW + cbase + 4 * l;
            const int slot = r & (DEPTH - 1);
            __pipeline_memcpy_async(&tile[w][slot][0][4 * l], Xb + off, 16);
            __pipeline_memcpy_async(&tile[w][slot][1][4 * l], Yb + off, 16);
        }
        __pipeline_commit();
    };

    auto dorow = [&](int r, int i, bool emit) {
        const int slot = r & (DEPTH - 1);
        const float* xr = &tile[w][slot][0][0];
        const float* yr = &tile[w][slot][1][0];
        const float2 a0 = *(const float2*)&xr[cl];
        const float2 a1 = *(const float2*)&xr[cl + 2];
        const float2 a2 = *(const float2*)&xr[cl + 4];
        const float2 a3 = *(const float2*)&xr[cl + 6];
        const float2 b0 = *(const float2*)&yr[cl];
        const float2 b1 = *(const float2*)&yr[cl + 2];
        const float2 b2 = *(const float2*)&yr[cl + 4];
        const float2 b3 = *(const float2*)&yr[cl + 6];
        const float x0=a0.x, x1=a0.y, x2=a1.x, x3=a1.y, x4=a2.x, x5=a2.y, x6=a3.x, x7=a3.y;
        const float y0=b0.x, y1=b0.y, y2=b1.x, y3=b1.y, y4=b2.x, y5=b2.y, y6=b3.x, y7=b3.y;

        // linear 7-tap sums: pairwise tree
        const float tx01 = x0 + x1, tx23 = x2 + x3, tx45 = x4 + x5;
        const float sx0 = (tx01 + tx23) + (tx45 + x6);
        const float sx1 = (sx0 - x0) + x7;
        const float ty01 = y0 + y1, ty23 = y2 + y3, ty45 = y4 + y5;
        const float sy0 = (ty01 + ty23) + (ty45 + y6);
        const float sy1 = (sy0 - y0) + y7;

        // p = x^2+y^2 window sum: two parallel chains
        float pA = x0 * x0;
        pA = fmaf(y0, y0, pA); pA = fmaf(x1, x1, pA); pA = fmaf(y1, y1, pA);
        pA = fmaf(x2, x2, pA); pA = fmaf(y2, y2, pA); pA = fmaf(x3, x3, pA);
        float pB = y3 * y3;
        pB = fmaf(x4, x4, pB); pB = fmaf(y4, y4, pB); pB = fmaf(x5, x5, pB);
        pB = fmaf(y5, y5, pB); pB = fmaf(x6, x6, pB); pB = fmaf(y6, y6, pB);
        const float sp0 = pA + pB;
        const float p0 = fmaf(y0, y0, x0 * x0);
        const float p7 = fmaf(y7, y7, x7 * x7);
        const float sp1 = (sp0 - p0) + p7;

        // q = x*y window sum: 4+3 parallel chains
        float qA = x0 * y0;
        qA = fmaf(x1, y1, qA); qA = fmaf(x2, y2, qA); qA = fmaf(x3, y3, qA);
        float qB = x4 * y4;
        qB = fmaf(x5, y5, qB); qB = fmaf(x6, y6, qB);
        const float sq0 = qA + qB;
        const float sq1 = fmaf(x7, y7, sq0 - x0 * y0);

        // vertical running windows
        Wx0 += sx0 - rx0[i]; rx0[i] = sx0;
        Wx1 += sx1 - rx1[i]; rx1[i] = sx1;
        Wy0 += sy0 - ry0[i]; ry0[i] = sy0;
        Wy1 += sy1 - ry1[i]; ry1[i] = sy1;
        Wp0 += sp0 - rp0[i]; rp0[i] = sp0;
        Wp1 += sp1 - rp1[i]; rp1[i] = sp1;
        Wq0 += sq0 - rq0[i]; rq0[i] = sq0;
        Wq1 += sq1 - rq1[i]; rq1[i] = sq1;

        if (emit) {
            // scale-free SSIM (x 49^2)
            const float pxy0 = Wx0 * Wy0;
            const float pss0 = fmaf(Wx0, Wx0, Wy0 * Wy0);
            const float N1a = fmaf(2.0f, pxy0, C1s);
            const float D1a = pss0 + C1s;
            const float N2a = fmaf(covn2, fmaf(49.0f, Wq0, -pxy0), C2s);
            const float D2a = fmaf(covn,  fmaf(49.0f, Wp0, -pss0), C2s);
            const float Na = N1a * N2a;
            const float Da = D1a * D2a;
            const float pxy1 = Wx1 * Wy1;
            const float pss1 = fmaf(Wx1, Wx1, Wy1 * Wy1);
            const float N1b = fmaf(2.0f, pxy1, C1s);
            const float D1b = pss1 + C1s;
            const float N2b = fmaf(covn2, fmaf(49.0f, Wq1, -pxy1), C2s);
            const float D2b = fmaf(covn,  fmaf(49.0f, Wp1, -pss1), C2s);
            const float Nb = N1b * N2b;
            const float Db = D1b * D2b;
            // 2 cols -> one rational; pair rows -> 1 divide per 4 px
            const float n2r = fmaf(Na, Db, Nb * Da);
            const float d2r = Da * Db;
            if (have) {
                acc += __fdividef(fmaf(pn, d2r, n2r * pd), pd * d2r);
                have = false;
            } else {
                pn = n2r; pd = d2r; have = true;
            }
        }
    };

    // ---- prologue: stage rows 0..6 (7 commit groups in flight) ----
#pragma unroll
    for (int r = 0; r < 7; r++) stage(r);

    // block 0 (rows 0..6): only row 6 emits
#pragma unroll
    for (int i = 0; i < WIN; i++) {
        __pipeline_wait_prior(6);
        __syncwarp();
        dorow(i, i, i == WIN - 1);
        stage(i + 7);
    }
    // blocks 1..5 (rows 7..41): all emit
    for (int blk = 1; blk < 6; blk++) {
        const int rb = blk * WIN;
#pragma unroll
        for (int i = 0; i < WIN; i++) {
            __pipeline_wait_prior(6);
            __syncwarp();
            dorow(rb + i, i, true);
            stage(rb + i + 7);
        }
    }
    // tail block (rows 42..47, ring slots 0..5): all emit
#pragma unroll
    for (int i = 0; i < 6; i++) {
        __pipeline_wait_prior(6);
        __syncwarp();
        dorow(42 + i, i, true);
        stage(49 + i);   // >= INROWS: empty commit keeps accounting aligned
    }
    __pipeline_wait_prior(0);

    if (have) acc += __fdividef(pn, pd);
    if (cbase + cl + 1 >= OW) acc = 0.f;  // invalid cols (incl. zero-pad region)

    // block reduction -> per-CTA partial
#pragma unroll
    for (int o = 16; o > 0; o >>= 1)
        acc += __shfl_xor_sync(0xffffffffu, acc, o);
    if (l == 0) warpsum[w] = acc;
    __syncthreads();
    const int cta = b * NBANDS + band;
    if (t == 0) {
        float s = 0.f;
#pragma unroll
        for (int ww = 0; ww < NWARPS; ww++) s += warpsum[ww];
        g_part[cta] = s;
        __threadfence();
        unsigned int n = atomicAdd(&g_count, 1u);
        is_last = (n == NCTAS - 1) ? 1 : 0;
    }
    __syncthreads();

    // last CTA: deterministic final reduction (576 = 3 * 192)
    if (is_last) {
        __threadfence();
        double s = 0.0;
        s += (double)g_part[t];
        s += (double)g_part[t + NTHREADS];
        s += (double)g_part[t + 2 * NTHREADS];
#pragma unroll
        for (int o = 16; o > 0; o >>= 1)
            s += __shfl_xor_sync(0xffffffffu, s, o);
        if (l == 0) dsum[w] = s;
        __syncthreads();
        if (t == 0) {
            double tot = 0.0;
#pragma unroll
            for (int ww = 0; ww < NWARPS; ww++) tot += dsum[ww];
            out[0] = (float)(1.0 - tot / ((double)BATCH * OH * OW));
            g_count = 0;   // reset for next graph replay
        }
    }
}

extern "C" void kernel_launch(void* const* d_in, const int* in_sizes, int n_in,
                              void* d_out, int out_size)
{
    const float* X  = (const float*)d_in[0];
    const float* Y  = (const float*)d_in[1];
    const float* dr = (const float*)d_in[2];
    float* out = (float*)d_out;

    dim3 grid(NBANDS, BATCH);
    ssim_main_kernel<<<grid, NTHREADS>>>(X, Y, dr, out);
}